// round 11
// baseline (speedup 1.0000x reference)
#include <cuda_runtime.h>
#include <cuda_bf16.h>
#include <cstdint>

#define B_    256
#define N_    32
#define DH_   128
#define E_    496
#define KH    256     // DIM_HID
#define NO    96      // DIM_OUT
#define AOUT  12
#define ETILE 62      // edges per tile-job
#define MR    124     // 2*ETILE real rows
#define LDP   98      // Ps pitch (floats)
#define JTILE 64
#define LDW1  257
#define TILES_TOTAL 2048   // B_ * (E_/ETILE)
#define CONS  384          // consumer threads (12 warps); producers = 128 (4 warps)

#define AHALF   65536                  // one K-half A buffer: 128 rows x 512B
#define B_OFF   (2 * AHALF)            // 131072
#define B_REGION 98304                 // NO * 1024
#define SMEM_EDGE (B_OFF + B_REGION)   // 229376

// named barriers
#define BAR_F0 1
#define BAR_F1 2
#define BAR_E0 3
#define BAR_C  4
#define BAR_PD 5

// -------- device scratch --------
__device__ float g_u[2u * B_ * N_ * KH];                    // [s][b][n][k]; s0 has +b1 folded
__device__ __align__(16) unsigned char g_w2i[NO * 1024];    // W2 hi/lo bf16 interleaved, XOR-swizzled
__device__ int g_ef[E_], g_et[E_];

// -------- helpers --------
__device__ __forceinline__ uint32_t smem_u32(const void* p) {
    uint32_t a;
    asm("{ .reg .u64 t; cvta.to.shared.u64 t, %1; cvt.u32.u64 %0, t; }" : "=r"(a) : "l"(p));
    return a;
}
__device__ __forceinline__ void cp_async16(uint32_t dst, const void* src) {
    asm volatile("cp.async.cg.shared.global [%0], [%1], 16;" :: "r"(dst), "l"(src) : "memory");
}
__device__ __forceinline__ void bar_sync(int id, int cnt) {
    asm volatile("bar.sync %0, %1;" :: "r"(id), "r"(cnt) : "memory");
}
__device__ __forceinline__ void bar_arrive(int id, int cnt) {
    asm volatile("bar.arrive %0, %1;" :: "r"(id), "r"(cnt) : "memory");
}
__device__ __forceinline__ void mma16816(float* c,
                                         uint32_t a0, uint32_t a1, uint32_t a2, uint32_t a3,
                                         uint32_t b0, uint32_t b1) {
    asm volatile(
        "mma.sync.aligned.m16n8k16.row.col.f32.bf16.bf16.f32 "
        "{%0,%1,%2,%3}, {%4,%5,%6,%7}, {%8,%9}, {%0,%1,%2,%3};"
        : "+f"(c[0]), "+f"(c[1]), "+f"(c[2]), "+f"(c[3])
        : "r"(a0), "r"(a1), "r"(a2), "r"(a3), "r"(b0), "r"(b1));
}
__device__ __forceinline__ uint32_t pkbf(float hi1, float hi0) {
    return ((uint32_t)__bfloat16_as_ushort(__float2bfloat16(hi1)) << 16) |
           __bfloat16_as_ushort(__float2bfloat16(hi0));
}

// -------- prep: normalize edge dtype (int32 vs int64) --------
__global__ void prep_edges(const int* __restrict__ efw, const int* __restrict__ etw) {
    int bad = 0;
    for (int t = threadIdx.x; t < E_; t += blockDim.x)
        if (t & 1)
            if (efw[t] != 0 || etw[t] != 0) bad = 1;
    int is32 = __syncthreads_or(bad);
    for (int e = threadIdx.x; e < E_; e += blockDim.x) {
        g_ef[e] = is32 ? efw[e] : efw[2 * e];
        g_et[e] = is32 ? etw[e] : etw[2 * e];
    }
}

// -------- prep: W2 -> interleaved hi/lo bf16 cells, XOR-swizzled --------
__global__ void prep_w2(const float* __restrict__ W2) {
    int idx = blockIdx.x * 256 + threadIdx.x;    // n*256 + k
    if (idx >= NO * KH) return;
    int n = idx >> 8, k = idx & 255;
    float v = W2[idx];
    __nv_bfloat16 hi = __float2bfloat16(v);
    __nv_bfloat16 lo = __float2bfloat16(v - __bfloat162float(hi));
    uint32_t kp   = (uint32_t)(k >> 1);
    uint32_t phys = kp ^ (((uint32_t)n & 3u) << 2);
    uint32_t cell = (uint32_t)n * 1024 + phys * 8 + (uint32_t)(k & 1) * 2;
    *(__nv_bfloat16*)(g_w2i + cell)     = hi;
    *(__nv_bfloat16*)(g_w2i + cell + 4) = lo;
}

// -------- stage A: node projections (b1 folded into u1 plane) --------
__global__ void __launch_bounds__(256) node_proj(const float* __restrict__ h,
                                                 const float* __restrict__ W1,
                                                 const float* __restrict__ b1) {
    extern __shared__ float smf[];
    float* hsA = smf;                   // 32*128
    float* w1s = smf + N_ * DH_;        // 64*LDW1

    int b  = blockIdx.y;
    int j0 = blockIdx.x * JTILE;
    int tid = threadIdx.x;

    for (int i = tid; i < N_ * DH_; i += 256)
        hsA[i] = h[(size_t)b * N_ * DH_ + i];
    for (int i = tid; i < JTILE * 256; i += 256) {
        int r = i >> 8, c = i & 255;
        w1s[r * LDW1 + c] = W1[(size_t)(j0 + r) * 256 + c];
    }
    __syncthreads();

    int jl = tid & 63;
    int ng = tid >> 6;
    float acc1[8], acc2[8];
#pragma unroll
    for (int i = 0; i < 8; i++) { acc1[i] = 0.f; acc2[i] = 0.f; }

    const float* w1row = &w1s[jl * LDW1];
    const float* hbase = &hsA[ng * 8 * DH_];
#pragma unroll 4
    for (int k = 0; k < DH_; k++) {
        float wa = w1row[k];
        float wb = w1row[k + 128];
#pragma unroll
        for (int nn = 0; nn < 8; nn++) {
            float hv = hbase[nn * DH_ + k];
            acc1[nn] = fmaf(wa, hv, acc1[nn]);
            acc2[nn] = fmaf(wb, hv, acc2[nn]);
        }
    }
    int j = j0 + jl;
    float b1v = b1[j];
#pragma unroll
    for (int nn = 0; nn < 8; nn++) {
        int n = ng * 8 + nn;
        g_u[(size_t)(b * N_ + n) * KH + j] = acc1[nn] + b1v;
        g_u[(size_t)B_ * N_ * KH + (size_t)(b * N_ + n) * KH + j] = acc2[nn];
    }
}

// -------- producer: build one K-half of A (bf16 hi/lo interleaved, swizzled) --------
__device__ __forceinline__ void build_half(unsigned char* Ah, const float* __restrict__ u1b,
                                           const float* __restrict__ u2b,
                                           int e0, int h, int tp) {
#pragma unroll 2
    for (int i = tp; i < MR * 32; i += 128) {
        int m = i >> 5, kq = i & 31;
        int el = (m < ETILE) ? m : m - ETILE;
        int nf = __ldg(&g_ef[e0 + el]);
        int nt = __ldg(&g_et[e0 + el]);
        if (m >= ETILE) { int tmp = nf; nf = nt; nt = tmp; }
        float4 ua = __ldg((const float4*)(u1b + nf * KH + h * 128 + kq * 4));
        float4 ub = __ldg((const float4*)(u2b + nt * KH + h * 128 + kq * 4));
        float v0 = fmaxf(ua.x + ub.x, 0.f), v1 = fmaxf(ua.y + ub.y, 0.f);
        float v2 = fmaxf(ua.z + ub.z, 0.f), v3 = fmaxf(ua.w + ub.w, 0.f);
        __nv_bfloat16 h0 = __float2bfloat16(v0), h1 = __float2bfloat16(v1);
        __nv_bfloat16 h2 = __float2bfloat16(v2), h3 = __float2bfloat16(v3);
        uint4 cell;
        cell.x = ((uint32_t)__bfloat16_as_ushort(h1) << 16) | __bfloat16_as_ushort(h0);
        cell.z = ((uint32_t)__bfloat16_as_ushort(h3) << 16) | __bfloat16_as_ushort(h2);
        cell.y = pkbf(v1 - __bfloat162float(h1), v0 - __bfloat162float(h0));
        cell.w = pkbf(v3 - __bfloat162float(h3), v2 - __bfloat162float(h2));
        uint32_t phys = ((uint32_t)(kq << 1)) ^ (((uint32_t)m & 3u) << 2);
        *(uint4*)(Ah + (uint32_t)m * 512 + phys * 8) = cell;
    }
}

// -------- stage B: persistent warp-specialized HMMA GEMM + payoff --------
__global__ void __launch_bounds__(512, 1) edge_gemm(const float* __restrict__ b2,
                                                    float* __restrict__ out) {
    extern __shared__ unsigned char sm[];
    unsigned char* Bsm = sm + B_OFF;           // NO x 1024B (swizzled)
    float* Ps = (float*)(sm + AHALF);          // reuses A1 half-buffer

    __shared__ float s_b2[NO];

    int tid = threadIdx.x;
    int bid = blockIdx.x;
    int grid = gridDim.x;
    int nt = (TILES_TOTAL - bid + grid - 1) / grid;

    // ---- init: B copy (once), b2, zero A pad rows 124..127 of both halves ----
    {
        uint32_t bdst = smem_u32(Bsm);
        for (int i = tid; i < B_REGION / 16; i += 512)
            cp_async16(bdst + (uint32_t)i * 16, g_w2i + (uint32_t)i * 16);
        asm volatile("cp.async.commit_group;" ::: "memory");
        if (tid < NO) s_b2[tid] = b2[tid];
        if (tid < 256) {
            int g = tid >> 7, j = tid & 127;
            *(uint4*)(sm + (uint32_t)g * AHALF + 124u * 512 + (uint32_t)j * 16) =
                make_uint4(0u, 0u, 0u, 0u);
        }
        asm volatile("cp.async.wait_group 0;" ::: "memory");
        __syncthreads();
    }

    if (tid >= CONS) {
        // ================= producer (4 warps, 128 threads) =================
        int tp = tid - CONS;
        for (int t = 0; t < nt; t++) {
            int tile = bid + t * grid;
            int b = tile >> 3, e0 = (tile & 7) * ETILE;
            const float* u1b = g_u + (size_t)b * N_ * KH;
            const float* u2b = g_u + (size_t)B_ * N_ * KH + (size_t)b * N_ * KH;

            if (t > 0) bar_sync(BAR_E0, 512);          // A0 free
            build_half(sm, u1b, u2b, e0, 0, tp);
            __threadfence_block();
            bar_arrive(BAR_F0, 512);

            if (t > 0) bar_sync(BAR_PD, 512);          // Ps/A1 free
            build_half(sm + AHALF, u1b, u2b, e0, 1, tp);
            __threadfence_block();
            bar_arrive(BAR_F1, 512);
        }
    } else {
        // ================= consumer (12 warps, 384 threads) =================
        int wid = tid >> 5, lid = tid & 31;
        int m0 = (wid & 3) * 32;
        int n0 = (wid >> 2) * 32;
        int lr = lid >> 2;              // 0..7
        int lc = lid & 3;               // 0..3
        uint32_t x4 = ((uint32_t)lr & 3u) << 2;
        uint32_t q  = (uint32_t)lc | (x4 & 4u);
        uint32_t x8 = x4 & 8u;

        const unsigned char* br0 = Bsm + (uint32_t)(n0 + lr) * 1024;
        const unsigned char* br1 = br0 + 8 * 1024;
        const unsigned char* br2 = br0 + 16 * 1024;
        const unsigned char* br3 = br0 + 24 * 1024;

        for (int t = 0; t < nt; t++) {
            int tile = bid + t * grid;
            int b = tile >> 3, e0 = (tile & 7) * ETILE;

            float acc[2][4][4];
#pragma unroll
            for (int fr = 0; fr < 2; fr++)
#pragma unroll
                for (int tt = 0; tt < 4; tt++)
#pragma unroll
                    for (int c = 0; c < 4; c++) acc[fr][tt][c] = 0.f;

#pragma unroll
            for (int h = 0; h < 2; h++) {
                bar_sync(h == 0 ? BAR_F0 : BAR_F1, 512);
                const unsigned char* ar0 = sm + (uint32_t)h * AHALF + (uint32_t)(m0 + lr) * 512;
                const unsigned char* ar1 = ar0 + 8 * 512;
                const unsigned char* ar2 = ar0 + 16 * 512;
                const unsigned char* ar3 = ar0 + 24 * 512;

                uint2 Af[2][8], Bf[2][8];
#define LOAD_FRAGS(buf, s_) do {                                               \
        uint32_t oa  = ((((uint32_t)(s_) << 3) ^ x8) | q) << 3;                \
        uint32_t oa4 = oa ^ 32u;                                               \
        uint32_t ob  = ((((uint32_t)((h << 3) + (s_)) << 3) ^ x8) | q) << 3;   \
        uint32_t ob4 = ob ^ 32u;                                               \
        Af[buf][0] = *(const uint2*)(ar0 + oa);                                \
        Af[buf][1] = *(const uint2*)(ar1 + oa);                                \
        Af[buf][2] = *(const uint2*)(ar0 + oa4);                               \
        Af[buf][3] = *(const uint2*)(ar1 + oa4);                               \
        Af[buf][4] = *(const uint2*)(ar2 + oa);                                \
        Af[buf][5] = *(const uint2*)(ar3 + oa);                                \
        Af[buf][6] = *(const uint2*)(ar2 + oa4);                               \
        Af[buf][7] = *(const uint2*)(ar3 + oa4);                               \
        Bf[buf][0] = *(const uint2*)(br0 + ob);                                \
        Bf[buf][1] = *(const uint2*)(br0 + ob4);                               \
        Bf[buf][2] = *(const uint2*)(br1 + ob);                                \
        Bf[buf][3] = *(const uint2*)(br1 + ob4);                               \
        Bf[buf][4] = *(const uint2*)(br2 + ob);                                \
        Bf[buf][5] = *(const uint2*)(br2 + ob4);                               \
        Bf[buf][6] = *(const uint2*)(br3 + ob);                                \
        Bf[buf][7] = *(const uint2*)(br3 + ob4);                               \
    } while (0)

                LOAD_FRAGS(0, 0);
#pragma unroll
                for (int s = 0; s < 8; s++) {
                    int cur = s & 1;
                    if (s < 7) LOAD_FRAGS(cur ^ 1, s + 1);
#pragma unroll
                    for (int fr = 0; fr < 2; fr++) {
                        uint2 a0 = Af[cur][fr * 4 + 0];
                        uint2 a1 = Af[cur][fr * 4 + 1];
                        uint2 a2 = Af[cur][fr * 4 + 2];
                        uint2 a3 = Af[cur][fr * 4 + 3];
#pragma unroll
                        for (int tt = 0; tt < 4; tt++) {
                            uint2 b0 = Bf[cur][tt * 2 + 0];
                            uint2 b1 = Bf[cur][tt * 2 + 1];
                            mma16816(acc[fr][tt], a0.x, a1.x, a2.x, a3.x, b0.x, b1.x);
                            mma16816(acc[fr][tt], a0.y, a1.y, a2.y, a3.y, b0.x, b1.x);
                            mma16816(acc[fr][tt], a0.x, a1.x, a2.x, a3.x, b0.y, b1.y);
                        }
                    }
                }
#undef LOAD_FRAGS
                if (h == 0) bar_arrive(BAR_E0, 512);
            }

            bar_sync(BAR_C, CONS);      // all consumers done reading A1

            // epilogue: acc (+b2) -> Ps
#pragma unroll
            for (int fr = 0; fr < 2; fr++) {
#pragma unroll
                for (int tt = 0; tt < 4; tt++) {
                    int mrow = m0 + fr * 16 + lr;
                    int col  = n0 + tt * 8 + lc * 2;
                    float bx = s_b2[col], by = s_b2[col + 1];
                    if (mrow < MR)
                        *(float2*)(Ps + mrow * LDP + col) =
                            make_float2(acc[fr][tt][0] + bx, acc[fr][tt][1] + by);
                    if (mrow + 8 < MR)
                        *(float2*)(Ps + (mrow + 8) * LDP + col) =
                            make_float2(acc[fr][tt][2] + bx, acc[fr][tt][3] + by);
                }
            }
            bar_sync(BAR_C, CONS);      // Ps complete

            // payoff
            for (int pr = tid; pr < ETILE * AOUT; pr += CONS) {
                int el = pr / AOUT;
                int i  = pr - el * AOUT;
                const float* P0 = &Ps[el * LDP];
                const float* P1 = &Ps[(ETILE + el) * LDP];
                float a0[4], a1[4];
#pragma unroll
                for (int r = 0; r < 4; r++) {
                    a0[r] = P0[24 * r + i];
                    a1[r] = P1[24 * r + 12 + i];
                }
                float res[12];
#pragma unroll
                for (int j = 0; j < 12; j++) {
                    float s = 0.f;
#pragma unroll
                    for (int r = 0; r < 4; r++)
                        s = fmaf(a0[r], P0[24 * r + 12 + j], fmaf(a1[r], P1[24 * r + j], s));
                    res[j] = 0.5f * s;
                }
                float4* op = reinterpret_cast<float4*>(
                    out + ((size_t)(b * E_ + e0 + el) * AOUT + i) * AOUT);
                op[0] = make_float4(res[0], res[1], res[2],  res[3]);
                op[1] = make_float4(res[4], res[5], res[6],  res[7]);
                op[2] = make_float4(res[8], res[9], res[10], res[11]);
            }
            bar_arrive(BAR_PD, 512);
        }
    }
}

// -------- launch --------
extern "C" void kernel_launch(void* const* d_in, const int* in_sizes, int n_in,
                              void* d_out, int out_size) {
    const float* h  = (const float*)d_in[0];
    const float* W1 = (const float*)d_in[1];
    const float* b1 = (const float*)d_in[2];
    const float* W2 = (const float*)d_in[3];
    const float* b2 = (const float*)d_in[4];
    const int*   ef = (const int*)d_in[5];
    const int*   et = (const int*)d_in[6];
    float* out = (float*)d_out;

    const int SMEM_A = (N_ * DH_ + JTILE * LDW1) * 4;      // 82,176 B

    cudaFuncSetAttribute(node_proj, cudaFuncAttributeMaxDynamicSharedMemorySize, SMEM_A);
    cudaFuncSetAttribute(edge_gemm, cudaFuncAttributeMaxDynamicSharedMemorySize, SMEM_EDGE);

    int dev = 0, nsm = 148;
    cudaGetDevice(&dev);
    cudaDeviceGetAttribute(&nsm, cudaDevAttrMultiProcessorCount, dev);

    prep_edges<<<1, 256>>>(ef, et);
    prep_w2<<<(NO * KH + 255) / 256, 256>>>(W2);
    node_proj<<<dim3(KH / JTILE, B_), 256, SMEM_A>>>(h, W1, b1);
    edge_gemm<<<nsm, 512, SMEM_EDGE>>>(b2, out);
}

// round 12
// speedup vs baseline: 1.0955x; 1.0955x over previous
#include <cuda_runtime.h>
#include <cuda_bf16.h>
#include <cstdint>

#define B_    256
#define N_    32
#define DH_   128
#define E_    496
#define KH    256     // DIM_HID
#define NO    96      // DIM_OUT
#define AOUT  12
#define ETILE 62      // edges per block
#define MR    124     // 2*ETILE real rows
#define MPAD  128     // A rows allocated
#define LDP   98      // Ps pitch (floats)
#define JTILE 64
#define LDW1I 258     // interleaved W1 pitch (floats, even)

#define A_REGION (MPAD * 1024)            // 131072
#define B_REGION (NO * 1024)              // 98304
#define SMEM_EDGE (A_REGION + B_REGION)   // 229376
#define SMEM_NP  ((N_ * DH_ + JTILE * LDW1I) * 4)   // 16384 + 66048 = 82432

// -------- device scratch --------
__device__ float g_u[2u * B_ * N_ * KH];                    // [s][b][n][k]; s0 has +b1 folded
__device__ __align__(16) unsigned char g_w2i[NO * 1024];    // W2 hi/lo bf16 interleaved, XOR-swizzled
__device__ int g_ef[E_], g_et[E_];

// -------- helpers --------
__device__ __forceinline__ uint32_t smem_u32(const void* p) {
    uint32_t a;
    asm("{ .reg .u64 t; cvta.to.shared.u64 t, %1; cvt.u32.u64 %0, t; }" : "=r"(a) : "l"(p));
    return a;
}
__device__ __forceinline__ void cp_async16(uint32_t dst, const void* src) {
    asm volatile("cp.async.cg.shared.global [%0], [%1], 16;" :: "r"(dst), "l"(src) : "memory");
}
__device__ __forceinline__ void mma16816(float* c,
                                         uint32_t a0, uint32_t a1, uint32_t a2, uint32_t a3,
                                         uint32_t b0, uint32_t b1) {
    asm volatile(
        "mma.sync.aligned.m16n8k16.row.col.f32.bf16.bf16.f32 "
        "{%0,%1,%2,%3}, {%4,%5,%6,%7}, {%8,%9}, {%0,%1,%2,%3};"
        : "+f"(c[0]), "+f"(c[1]), "+f"(c[2]), "+f"(c[3])
        : "r"(a0), "r"(a1), "r"(a2), "r"(a3), "r"(b0), "r"(b1));
}
__device__ __forceinline__ uint32_t pkbf(float hi1, float hi0) {
    return ((uint32_t)__bfloat16_as_ushort(__float2bfloat16(hi1)) << 16) |
           __bfloat16_as_ushort(__float2bfloat16(hi0));
}
// f32x2 helpers
__device__ __forceinline__ unsigned long long pk2(float x) {
    unsigned long long r;
    asm("mov.b64 %0, {%1,%2};" : "=l"(r) : "f"(x), "f"(x));
    return r;
}
__device__ __forceinline__ void ffma2(unsigned long long& d,
                                      unsigned long long a, unsigned long long b) {
    asm("fma.rn.f32x2 %0, %1, %2, %0;" : "+l"(d) : "l"(a), "l"(b));
}
__device__ __forceinline__ float2 upk(unsigned long long v) {
    float2 r;
    asm("mov.b64 {%0,%1}, %2;" : "=f"(r.x), "=f"(r.y) : "l"(v));
    return r;
}

// -------- merged prep: edges (block 96) + W2 interleave/swizzle (blocks 0..95) --------
__global__ void prep_all(const float* __restrict__ W2,
                         const int* __restrict__ efw, const int* __restrict__ etw) {
    if (blockIdx.x == 96) {
        int bad = 0;
        for (int t = threadIdx.x; t < E_; t += blockDim.x)
            if (t & 1)
                if (efw[t] != 0 || etw[t] != 0) bad = 1;
        int is32 = __syncthreads_or(bad);
        for (int e = threadIdx.x; e < E_; e += blockDim.x) {
            g_ef[e] = is32 ? efw[e] : efw[2 * e];
            g_et[e] = is32 ? etw[e] : etw[2 * e];
        }
        return;
    }
    int idx = blockIdx.x * 256 + threadIdx.x;    // n*256 + k
    int n = idx >> 8, k = idx & 255;
    float v = W2[idx];
    __nv_bfloat16 hi = __float2bfloat16(v);
    __nv_bfloat16 lo = __float2bfloat16(v - __bfloat162float(hi));
    uint32_t kp   = (uint32_t)(k >> 1);
    uint32_t phys = kp ^ (((uint32_t)n & 3u) << 2);
    uint32_t cell = (uint32_t)n * 1024 + phys * 8 + (uint32_t)(k & 1) * 2;
    *(__nv_bfloat16*)(g_w2i + cell)     = hi;
    *(__nv_bfloat16*)(g_w2i + cell + 4) = lo;
}

// -------- stage A: node projections, f32x2 packed (b1 folded into u1 plane) --------
__global__ void __launch_bounds__(256) node_proj(const float* __restrict__ h,
                                                 const float* __restrict__ W1,
                                                 const float* __restrict__ b1) {
    extern __shared__ float smf[];
    float* hsT = smf;                   // [k][n] : 128 x 32
    float* w1s = smf + N_ * DH_;        // 64 rows x 258 (interleaved {wa,wb} pairs)

    int b  = blockIdx.y;
    int j0 = blockIdx.x * JTILE;
    int tid = threadIdx.x;

    // h transposed into smem: hsT[k*32 + n]
    for (int i = tid; i < N_ * DH_; i += 256) {
        int n = i >> 7, k = i & 127;
        hsT[k * N_ + n] = h[(size_t)b * N_ * DH_ + i];
    }
    // W1 interleaved: row r slot kp holds {W1[j0+r][kp], W1[j0+r][kp+128]}
    for (int i = tid; i < JTILE * 256; i += 256) {
        int r = i >> 8, c = i & 255;
        w1s[r * LDW1I + ((c & 127) << 1) + (c >> 7)] = W1[(size_t)(j0 + r) * 256 + c];
    }
    __syncthreads();

    int jl = tid & 63;
    int ng = tid >> 6;          // node group (8 nodes)
    unsigned long long acc[8];
#pragma unroll
    for (int i = 0; i < 8; i++) acc[i] = 0ull;

    const unsigned long long* wrow =
        reinterpret_cast<const unsigned long long*>(w1s + jl * LDW1I);
    const float* hb = hsT + ng * 8;

#pragma unroll 4
    for (int k = 0; k < DH_; k++) {
        unsigned long long w = wrow[k];                       // {wa, wb} LDS.64
        float4 h0 = *(const float4*)(hb + k * N_);            // broadcast
        float4 h1 = *(const float4*)(hb + k * N_ + 4);
        ffma2(acc[0], pk2(h0.x), w);
        ffma2(acc[1], pk2(h0.y), w);
        ffma2(acc[2], pk2(h0.z), w);
        ffma2(acc[3], pk2(h0.w), w);
        ffma2(acc[4], pk2(h1.x), w);
        ffma2(acc[5], pk2(h1.y), w);
        ffma2(acc[6], pk2(h1.z), w);
        ffma2(acc[7], pk2(h1.w), w);
    }

    int j = j0 + jl;
    float b1v = b1[j];
#pragma unroll
    for (int nn = 0; nn < 8; nn++) {
        int n = ng * 8 + nn;
        float2 v = upk(acc[nn]);
        g_u[(size_t)(b * N_ + n) * KH + j] = v.x + b1v;
        g_u[(size_t)B_ * N_ * KH + (size_t)(b * N_ + n) * KH + j] = v.y;
    }
}

// -------- stage B: HMMA bf16x3 GEMM, cp.async B + direct-L2 A build --------
__global__ void __launch_bounds__(512, 1) edge_gemm(const float* __restrict__ b2,
                                                    float* __restrict__ out) {
    extern __shared__ unsigned char sm[];
    unsigned char* Asm = sm;                    // MPAD rows x 1024B (hi/lo interleaved, swizzled)
    unsigned char* Bsm = sm + A_REGION;         // NO x 1024B (swizzled)
    float* Ps  = (float*)Asm;                   // P result reuses A region post-MMA

    __shared__ int s_ef[ETILE], s_et[ETILE];
    __shared__ float s_b2[NO];

    int b = blockIdx.y, e0 = blockIdx.x * ETILE;
    int tid = threadIdx.x;
    int wid = tid >> 5, lid = tid & 31;

    // ---- kick off B copy (pre-swizzled, flat 96KB) via cp.async ----
    {
        uint32_t bdst = smem_u32(Bsm) + (uint32_t)tid * 16;
        const unsigned char* bsrc = g_w2i + (uint32_t)tid * 16;
#pragma unroll
        for (int i = 0; i < B_REGION / (512 * 16); i++) {
            cp_async16(bdst + i * 512 * 16, bsrc + i * 512 * 16);
        }
        asm volatile("cp.async.commit_group;" ::: "memory");
    }

    if (tid < ETILE) { s_ef[tid] = g_ef[e0 + tid]; s_et[tid] = g_et[e0 + tid]; }
    if (tid >= 128 && tid < 128 + NO) s_b2[tid - 128] = b2[tid - 128];
    __syncthreads();    // edge indices visible

    // ---- build A directly from g_u (L2): relu(u1+u2) -> interleaved hi/lo, swizzled ----
    const float* u1b = g_u + (size_t)b * N_ * KH;
    const float* u2b = g_u + (size_t)B_ * N_ * KH + (size_t)b * N_ * KH;
#pragma unroll 4
    for (int i = tid; i < MR * 64; i += 512) {
        int m = i >> 6, kq = i & 63;
        int el = (m < ETILE) ? m : m - ETILE;
        int nf, nt;
        if (m < ETILE) { nf = s_ef[el]; nt = s_et[el]; }
        else           { nf = s_et[el]; nt = s_ef[el]; }
        float4 ua = *(const float4*)(u1b + nf * KH + kq * 4);
        float4 ub = *(const float4*)(u2b + nt * KH + kq * 4);
        float v0 = fmaxf(ua.x + ub.x, 0.f), v1 = fmaxf(ua.y + ub.y, 0.f);
        float v2 = fmaxf(ua.z + ub.z, 0.f), v3 = fmaxf(ua.w + ub.w, 0.f);
        __nv_bfloat16 h0 = __float2bfloat16(v0), h1 = __float2bfloat16(v1);
        __nv_bfloat16 h2 = __float2bfloat16(v2), h3 = __float2bfloat16(v3);
        uint4 cell;
        cell.x = ((uint32_t)__bfloat16_as_ushort(h1) << 16) | __bfloat16_as_ushort(h0);
        cell.z = ((uint32_t)__bfloat16_as_ushort(h3) << 16) | __bfloat16_as_ushort(h2);
        cell.y = pkbf(v1 - __bfloat162float(h1), v0 - __bfloat162float(h0));
        cell.w = pkbf(v3 - __bfloat162float(h3), v2 - __bfloat162float(h2));
        uint32_t phys = ((uint32_t)(kq << 1)) ^ (((uint32_t)m & 3u) << 2);
        *(uint4*)(Asm + (uint32_t)m * 1024 + phys * 8) = cell;
    }
    asm volatile("cp.async.wait_group 0;" ::: "memory");
    __syncthreads();

    // ---- HMMA: 16 warps, warp tile m32 x n24, full K=256, double-buffered ----
    int m0 = (wid >> 2) * 32;
    int n0 = (wid & 3) * 24;
    int lr = lid >> 2;              // 0..7
    int lc = lid & 3;               // 0..3
    uint32_t x4 = ((uint32_t)lr & 3u) << 2;
    uint32_t q  = (uint32_t)lc | (x4 & 4u);
    uint32_t x8 = x4 & 8u;

    const unsigned char* arow0 = Asm + (uint32_t)(m0 + lr) * 1024;
    const unsigned char* arow1 = arow0 + 8 * 1024;
    const unsigned char* arow2 = arow0 + 16 * 1024;
    const unsigned char* arow3 = arow0 + 24 * 1024;
    const unsigned char* brow0 = Bsm + (uint32_t)(n0 + lr) * 1024;
    const unsigned char* brow1 = brow0 + 8 * 1024;
    const unsigned char* brow2 = brow0 + 16 * 1024;

    float acc[2][3][4];
#pragma unroll
    for (int fr = 0; fr < 2; fr++)
#pragma unroll
        for (int t = 0; t < 3; t++)
#pragma unroll
            for (int c = 0; c < 4; c++) acc[fr][t][c] = 0.f;

    uint2 Af[2][8];
    uint2 Bf[2][6];

#define LOAD_FRAGS(buf, st_) do {                                              \
        uint32_t off0 = ((((uint32_t)(st_) << 3) ^ x8) | q) << 3;              \
        uint32_t off4 = off0 ^ 32u;                                            \
        Af[buf][0] = *(const uint2*)(arow0 + off0);                            \
        Af[buf][1] = *(const uint2*)(arow1 + off0);                            \
        Af[buf][2] = *(const uint2*)(arow0 + off4);                            \
        Af[buf][3] = *(const uint2*)(arow1 + off4);                            \
        Af[buf][4] = *(const uint2*)(arow2 + off0);                            \
        Af[buf][5] = *(const uint2*)(arow3 + off0);                            \
        Af[buf][6] = *(const uint2*)(arow2 + off4);                            \
        Af[buf][7] = *(const uint2*)(arow3 + off4);                            \
        Bf[buf][0] = *(const uint2*)(brow0 + off0);                            \
        Bf[buf][1] = *(const uint2*)(brow0 + off4);                            \
        Bf[buf][2] = *(const uint2*)(brow1 + off0);                            \
        Bf[buf][3] = *(const uint2*)(brow1 + off4);                            \
        Bf[buf][4] = *(const uint2*)(brow2 + off0);                            \
        Bf[buf][5] = *(const uint2*)(brow2 + off4);                            \
    } while (0)

    LOAD_FRAGS(0, 0);
#pragma unroll
    for (int st = 0; st < 16; st++) {
        int cur = st & 1;
        if (st < 15) LOAD_FRAGS(cur ^ 1, st + 1);
#pragma unroll
        for (int fr = 0; fr < 2; fr++) {
            uint2 a0 = Af[cur][fr * 4 + 0];
            uint2 a1 = Af[cur][fr * 4 + 1];
            uint2 a2 = Af[cur][fr * 4 + 2];
            uint2 a3 = Af[cur][fr * 4 + 3];
#pragma unroll
            for (int t = 0; t < 3; t++) {
                uint2 b0 = Bf[cur][t * 2 + 0];
                uint2 b1 = Bf[cur][t * 2 + 1];
                mma16816(acc[fr][t], a0.x, a1.x, a2.x, a3.x, b0.x, b1.x);
                mma16816(acc[fr][t], a0.y, a1.y, a2.y, a3.y, b0.x, b1.x);
                mma16816(acc[fr][t], a0.x, a1.x, a2.x, a3.x, b0.y, b1.y);
            }
        }
    }
#undef LOAD_FRAGS

    __syncthreads();    // all smem reads of A/B done before Ps overwrite

    // ---- epilogue: direct store acc (+b2) into Ps ----
#pragma unroll
    for (int fr = 0; fr < 2; fr++) {
#pragma unroll
        for (int t = 0; t < 3; t++) {
            int mrow = m0 + fr * 16 + lr;
            int col  = n0 + t * 8 + lc * 2;
            float bx = s_b2[col], by = s_b2[col + 1];
            if (mrow < MR)
                *(float2*)(Ps + mrow * LDP + col) =
                    make_float2(acc[fr][t][0] + bx, acc[fr][t][1] + by);
            if (mrow + 8 < MR)
                *(float2*)(Ps + (mrow + 8) * LDP + col) =
                    make_float2(acc[fr][t][2] + bx, acc[fr][t][3] + by);
        }
    }
    __syncthreads();

    // ---- payoff ----
    for (int pr = tid; pr < ETILE * AOUT; pr += 512) {
        int el = pr / AOUT;
        int i  = pr - el * AOUT;
        const float* P0 = &Ps[el * LDP];
        const float* P1 = &Ps[(ETILE + el) * LDP];
        float a0[4], a1[4];
#pragma unroll
        for (int r = 0; r < 4; r++) {
            a0[r] = P0[24 * r + i];
            a1[r] = P1[24 * r + 12 + i];
        }
        float res[12];
#pragma unroll
        for (int j = 0; j < 12; j++) {
            float s = 0.f;
#pragma unroll
            for (int r = 0; r < 4; r++)
                s = fmaf(a0[r], P0[24 * r + 12 + j], fmaf(a1[r], P1[24 * r + j], s));
            res[j] = 0.5f * s;
        }
        float4* op = reinterpret_cast<float4*>(
            out + ((size_t)(b * E_ + e0 + el) * AOUT + i) * AOUT);
        op[0] = make_float4(res[0], res[1], res[2],  res[3]);
        op[1] = make_float4(res[4], res[5], res[6],  res[7]);
        op[2] = make_float4(res[8], res[9], res[10], res[11]);
    }
}

// -------- launch --------
extern "C" void kernel_launch(void* const* d_in, const int* in_sizes, int n_in,
                              void* d_out, int out_size) {
    const float* h  = (const float*)d_in[0];
    const float* W1 = (const float*)d_in[1];
    const float* b1 = (const float*)d_in[2];
    const float* W2 = (const float*)d_in[3];
    const float* b2 = (const float*)d_in[4];
    const int*   ef = (const int*)d_in[5];
    const int*   et = (const int*)d_in[6];
    float* out = (float*)d_out;

    cudaFuncSetAttribute(node_proj, cudaFuncAttributeMaxDynamicSharedMemorySize, SMEM_NP);
    cudaFuncSetAttribute(edge_gemm, cudaFuncAttributeMaxDynamicSharedMemorySize, SMEM_EDGE);

    prep_all<<<97, 256>>>(W2, ef, et);
    node_proj<<<dim3(KH / JTILE, B_), 256, SMEM_NP>>>(h, W1, b1);
    edge_gemm<<<dim3(E_ / ETILE, B_), 512, SMEM_EDGE>>>(b2, out);
}

// round 13
// speedup vs baseline: 1.2255x; 1.1187x over previous
#include <cuda_runtime.h>
#include <cuda_bf16.h>
#include <cstdint>

#define B_    256
#define N_    32
#define DH_   128
#define E_    496
#define KH    256     // DIM_HID
#define NO    96      // DIM_OUT
#define AOUT  12
#define ETILE 62      // edges per tile-job
#define MR    124     // 2*ETILE real rows
#define MPAD  128
#define JTILE 64
#define LDW1I 258
#define TILES_TOTAL 2048
#define MAXSM 192

#define A_REGION (MPAD * 1024)            // 131072
#define B_REGION (NO * 1024)              // 98304
#define SMEM_EDGE (A_REGION + B_REGION)   // 229376
#define SMEM_NP  ((N_ * DH_ + JTILE * LDW1I) * 4)

// -------- device scratch --------
__device__ float g_u[2u * B_ * N_ * KH];                    // [s][b][n][k]; s0 has +b1 folded
__device__ __align__(16) unsigned char g_w2i[NO * 1024];    // W2 hi/lo bf16 interleaved, swizzled
__device__ int g_ef[E_], g_et[E_];
__device__ __align__(16) float g_pscr[MAXSM * MR * NO];     // per-block P scratch (L2)

// -------- helpers --------
__device__ __forceinline__ uint32_t smem_u32(const void* p) {
    uint32_t a;
    asm("{ .reg .u64 t; cvta.to.shared.u64 t, %1; cvt.u32.u64 %0, t; }" : "=r"(a) : "l"(p));
    return a;
}
__device__ __forceinline__ void cp_async16(uint32_t dst, const void* src) {
    asm volatile("cp.async.cg.shared.global [%0], [%1], 16;" :: "r"(dst), "l"(src) : "memory");
}
__device__ __forceinline__ void mma16816(float* c,
                                         uint32_t a0, uint32_t a1, uint32_t a2, uint32_t a3,
                                         uint32_t b0, uint32_t b1) {
    asm volatile(
        "mma.sync.aligned.m16n8k16.row.col.f32.bf16.bf16.f32 "
        "{%0,%1,%2,%3}, {%4,%5,%6,%7}, {%8,%9}, {%0,%1,%2,%3};"
        : "+f"(c[0]), "+f"(c[1]), "+f"(c[2]), "+f"(c[3])
        : "r"(a0), "r"(a1), "r"(a2), "r"(a3), "r"(b0), "r"(b1));
}
__device__ __forceinline__ uint32_t cvt2bf(float lo, float hi) {
    uint32_t r;
    asm("cvt.rn.bf16x2.f32 %0, %1, %2;" : "=r"(r) : "f"(hi), "f"(lo));
    return r;
}
// f32x2 helpers (node_proj)
__device__ __forceinline__ unsigned long long pk2(float x) {
    unsigned long long r;
    asm("mov.b64 %0, {%1,%2};" : "=l"(r) : "f"(x), "f"(x));
    return r;
}
__device__ __forceinline__ void ffma2(unsigned long long& d,
                                      unsigned long long a, unsigned long long b) {
    asm("fma.rn.f32x2 %0, %1, %2, %0;" : "+l"(d) : "l"(a), "l"(b));
}
__device__ __forceinline__ float2 upk(unsigned long long v) {
    float2 r;
    asm("mov.b64 {%0,%1}, %2;" : "=f"(r.x), "=f"(r.y) : "l"(v));
    return r;
}

// -------- merged prep --------
__global__ void prep_all(const float* __restrict__ W2,
                         const int* __restrict__ efw, const int* __restrict__ etw) {
    if (blockIdx.x == 96) {
        int bad = 0;
        for (int t = threadIdx.x; t < E_; t += blockDim.x)
            if (t & 1)
                if (efw[t] != 0 || etw[t] != 0) bad = 1;
        int is32 = __syncthreads_or(bad);
        for (int e = threadIdx.x; e < E_; e += blockDim.x) {
            g_ef[e] = is32 ? efw[e] : efw[2 * e];
            g_et[e] = is32 ? etw[e] : etw[2 * e];
        }
        return;
    }
    int idx = blockIdx.x * 256 + threadIdx.x;    // n*256 + k
    int n = idx >> 8, k = idx & 255;
    float v = W2[idx];
    __nv_bfloat16 hi = __float2bfloat16(v);
    __nv_bfloat16 lo = __float2bfloat16(v - __bfloat162float(hi));
    uint32_t kp   = (uint32_t)(k >> 1);
    uint32_t phys = kp ^ (((uint32_t)n & 3u) << 2);
    uint32_t cell = (uint32_t)n * 1024 + phys * 8 + (uint32_t)(k & 1) * 2;
    *(__nv_bfloat16*)(g_w2i + cell)     = hi;
    *(__nv_bfloat16*)(g_w2i + cell + 4) = lo;
}

// -------- stage A: node projections, f32x2 packed --------
__global__ void __launch_bounds__(256) node_proj(const float* __restrict__ h,
                                                 const float* __restrict__ W1,
                                                 const float* __restrict__ b1) {
    extern __shared__ float smf[];
    float* hsT = smf;                   // [k][n]: 128 x 32
    float* w1s = smf + N_ * DH_;        // 64 x 258 interleaved {wa,wb}

    int b  = blockIdx.y;
    int j0 = blockIdx.x * JTILE;
    int tid = threadIdx.x;

    for (int i = tid; i < N_ * DH_; i += 256) {
        int n = i >> 7, k = i & 127;
        hsT[k * N_ + n] = h[(size_t)b * N_ * DH_ + i];
    }
    for (int i = tid; i < JTILE * 256; i += 256) {
        int r = i >> 8, c = i & 255;
        w1s[r * LDW1I + ((c & 127) << 1) + (c >> 7)] = W1[(size_t)(j0 + r) * 256 + c];
    }
    __syncthreads();

    int jl = tid & 63;
    int ng = tid >> 6;
    unsigned long long acc[8];
#pragma unroll
    for (int i = 0; i < 8; i++) acc[i] = 0ull;

    const unsigned long long* wrow =
        reinterpret_cast<const unsigned long long*>(w1s + jl * LDW1I);
    const float* hb = hsT + ng * 8;

#pragma unroll 4
    for (int k = 0; k < DH_; k++) {
        unsigned long long w = wrow[k];
        float4 h0 = *(const float4*)(hb + k * N_);
        float4 h1 = *(const float4*)(hb + k * N_ + 4);
        ffma2(acc[0], pk2(h0.x), w);
        ffma2(acc[1], pk2(h0.y), w);
        ffma2(acc[2], pk2(h0.z), w);
        ffma2(acc[3], pk2(h0.w), w);
        ffma2(acc[4], pk2(h1.x), w);
        ffma2(acc[5], pk2(h1.y), w);
        ffma2(acc[6], pk2(h1.z), w);
        ffma2(acc[7], pk2(h1.w), w);
    }

    int j = j0 + jl;
    float b1v = b1[j];
#pragma unroll
    for (int nn = 0; nn < 8; nn++) {
        int n = ng * 8 + nn;
        float2 v = upk(acc[nn]);
        g_u[(size_t)(b * N_ + n) * KH + j] = v.x + b1v;
        g_u[(size_t)B_ * N_ * KH + (size_t)(b * N_ + n) * KH + j] = v.y;
    }
}

// -------- A build for one tile (all 512 threads) --------
__device__ __forceinline__ void build_A(unsigned char* Asm, int b, int e0, int tid) {
    const float* u1b = g_u + (size_t)b * N_ * KH;
    const float* u2b = g_u + (size_t)B_ * N_ * KH + (size_t)b * N_ * KH;
#pragma unroll 4
    for (int i = tid; i < MR * 64; i += 512) {
        int m = i >> 6, kq = i & 63;
        int el = (m < ETILE) ? m : m - ETILE;
        int nf = __ldg(&g_ef[e0 + el]);
        int nt = __ldg(&g_et[e0 + el]);
        if (m >= ETILE) { int tmp = nf; nf = nt; nt = tmp; }
        float4 ua = __ldg((const float4*)(u1b + nf * KH + kq * 4));
        float4 ub = __ldg((const float4*)(u2b + nt * KH + kq * 4));
        float v0 = fmaxf(ua.x + ub.x, 0.f), v1 = fmaxf(ua.y + ub.y, 0.f);
        float v2 = fmaxf(ua.z + ub.z, 0.f), v3 = fmaxf(ua.w + ub.w, 0.f);
        uint4 cell;
        cell.x = cvt2bf(v0, v1);
        cell.z = cvt2bf(v2, v3);
        float h0f = __uint_as_float(cell.x << 16);
        float h1f = __uint_as_float(cell.x & 0xffff0000u);
        float h2f = __uint_as_float(cell.z << 16);
        float h3f = __uint_as_float(cell.z & 0xffff0000u);
        cell.y = cvt2bf(v0 - h0f, v1 - h1f);
        cell.w = cvt2bf(v2 - h2f, v3 - h3f);
        uint32_t phys = ((uint32_t)(kq << 1)) ^ (((uint32_t)m & 3u) << 2);
        *(uint4*)(Asm + (uint32_t)m * 1024 + phys * 8) = cell;
    }
}

// -------- stage B: persistent HMMA bf16x3 GEMM + pipelined build/payoff --------
__global__ void __launch_bounds__(512, 1) edge_gemm(const float* __restrict__ b2,
                                                    float* __restrict__ out) {
    extern __shared__ unsigned char sm[];
    unsigned char* Asm = sm;                    // MPAD x 1024B
    unsigned char* Bsm = sm + A_REGION;         // NO x 1024B

    __shared__ float s_b2[NO];

    int tid = threadIdx.x;
    int wid = tid >> 5, lid = tid & 31;
    int bid = blockIdx.x;
    int grid = gridDim.x;
    int nt = (TILES_TOTAL - bid + grid - 1) / grid;
    float* scr = g_pscr + (size_t)bid * (MR * NO);

    // ---- init: B copy once, b2, zero A pad rows ----
    {
        uint32_t bdst = smem_u32(Bsm);
        for (int i = tid; i < B_REGION / 16; i += 512)
            cp_async16(bdst + (uint32_t)i * 16, g_w2i + (uint32_t)i * 16);
        asm volatile("cp.async.commit_group;" ::: "memory");
        if (tid < NO) s_b2[tid] = b2[tid];
        if (tid < 256)
            *(uint4*)(Asm + 124u * 1024 + (uint32_t)tid * 16) = make_uint4(0u, 0u, 0u, 0u);
        asm volatile("cp.async.wait_group 0;" ::: "memory");
        __syncthreads();
    }

    // GEMM lane geometry
    int m0 = (wid >> 2) * 32;
    int n0 = (wid & 3) * 24;
    int lr = lid >> 2;
    int lc = lid & 3;
    uint32_t x4 = ((uint32_t)lr & 3u) << 2;
    uint32_t q  = (uint32_t)lc | (x4 & 4u);
    uint32_t x8 = x4 & 8u;

    const unsigned char* arow0 = Asm + (uint32_t)(m0 + lr) * 1024;
    const unsigned char* arow1 = arow0 + 8 * 1024;
    const unsigned char* arow2 = arow0 + 16 * 1024;
    const unsigned char* arow3 = arow0 + 24 * 1024;
    const unsigned char* brow0 = Bsm + (uint32_t)(n0 + lr) * 1024;
    const unsigned char* brow1 = brow0 + 8 * 1024;
    const unsigned char* brow2 = brow0 + 16 * 1024;

    // prologue: build first tile
    {
        int tile = bid;
        build_A(Asm, tile >> 3, (tile & 7) * ETILE, tid);
    }

    for (int it = 0; it < nt; it++) {
        int tile = bid + it * grid;
        int b = tile >> 3, e0 = (tile & 7) * ETILE;

        __syncthreads();    // A(it) built (and prior payoff's scratch reads done)

        // ---- GEMM ----
        float acc[2][3][4];
#pragma unroll
        for (int fr = 0; fr < 2; fr++)
#pragma unroll
            for (int t = 0; t < 3; t++)
#pragma unroll
                for (int c = 0; c < 4; c++) acc[fr][t][c] = 0.f;

        uint2 Af[2][8];
        uint2 Bf[2][6];
#define LOAD_FRAGS(buf, st_) do {                                              \
        uint32_t off0 = ((((uint32_t)(st_) << 3) ^ x8) | q) << 3;              \
        uint32_t off4 = off0 ^ 32u;                                            \
        Af[buf][0] = *(const uint2*)(arow0 + off0);                            \
        Af[buf][1] = *(const uint2*)(arow1 + off0);                            \
        Af[buf][2] = *(const uint2*)(arow0 + off4);                            \
        Af[buf][3] = *(const uint2*)(arow1 + off4);                            \
        Af[buf][4] = *(const uint2*)(arow2 + off0);                            \
        Af[buf][5] = *(const uint2*)(arow3 + off0);                            \
        Af[buf][6] = *(const uint2*)(arow2 + off4);                            \
        Af[buf][7] = *(const uint2*)(arow3 + off4);                            \
        Bf[buf][0] = *(const uint2*)(brow0 + off0);                            \
        Bf[buf][1] = *(const uint2*)(brow0 + off4);                            \
        Bf[buf][2] = *(const uint2*)(brow1 + off0);                            \
        Bf[buf][3] = *(const uint2*)(brow1 + off4);                            \
        Bf[buf][4] = *(const uint2*)(brow2 + off0);                            \
        Bf[buf][5] = *(const uint2*)(brow2 + off4);                            \
    } while (0)

        LOAD_FRAGS(0, 0);
#pragma unroll
        for (int st = 0; st < 16; st++) {
            int cur = st & 1;
            if (st < 15) LOAD_FRAGS(cur ^ 1, st + 1);
#pragma unroll
            for (int fr = 0; fr < 2; fr++) {
                uint2 a0 = Af[cur][fr * 4 + 0];
                uint2 a1 = Af[cur][fr * 4 + 1];
                uint2 a2 = Af[cur][fr * 4 + 2];
                uint2 a3 = Af[cur][fr * 4 + 3];
#pragma unroll
                for (int t = 0; t < 3; t++) {
                    uint2 b0 = Bf[cur][t * 2 + 0];
                    uint2 b1 = Bf[cur][t * 2 + 1];
                    mma16816(acc[fr][t], a0.x, a1.x, a2.x, a3.x, b0.x, b1.x);
                    mma16816(acc[fr][t], a0.y, a1.y, a2.y, a3.y, b0.x, b1.x);
                    mma16816(acc[fr][t], a0.x, a1.x, a2.x, a3.x, b0.y, b1.y);
                }
            }
        }
#undef LOAD_FRAGS

        // ---- epilogue: acc (+b2) -> gmem scratch ----
#pragma unroll
        for (int fr = 0; fr < 2; fr++) {
#pragma unroll
            for (int t = 0; t < 3; t++) {
                int mrow = m0 + fr * 16 + lr;
                int col  = n0 + t * 8 + lc * 2;
                float bx = s_b2[col], by = s_b2[col + 1];
                if (mrow < MR)
                    *(float2*)(scr + mrow * NO + col) =
                        make_float2(acc[fr][t][0] + bx, acc[fr][t][1] + by);
                if (mrow + 8 < MR)
                    *(float2*)(scr + (mrow + 8) * NO + col) =
                        make_float2(acc[fr][t][2] + bx, acc[fr][t][3] + by);
            }
        }
        __syncthreads();    // A reads done + P visible block-wide

        // ---- build next tile's A (overlaps payoff below) ----
        if (it + 1 < nt) {
            int tile2 = bid + (it + 1) * grid;
            build_A(Asm, tile2 >> 3, (tile2 & 7) * ETILE, tid);
        }

        // ---- payoff from gmem scratch ----
        for (int pr = tid; pr < ETILE * AOUT; pr += 512) {
            int el = pr / AOUT;
            int i  = pr - el * AOUT;
            const float*  P0  = scr + el * NO;
            const float*  P1  = P0 + ETILE * NO;
            const float4* p0v = (const float4*)P0;
            const float4* p1v = (const float4*)P1;
            float a0[4], a1[4];
#pragma unroll
            for (int r = 0; r < 4; r++) {
                a0[r] = __ldg(P0 + 24 * r + i);
                a1[r] = __ldg(P1 + 24 * r + 12 + i);
            }
            float res[12];
#pragma unroll
            for (int j = 0; j < 12; j++) res[j] = 0.f;
#pragma unroll
            for (int r = 0; r < 4; r++) {
                float4 x0 = __ldg(p0v + 6 * r + 3);
                float4 x1 = __ldg(p0v + 6 * r + 4);
                float4 x2 = __ldg(p0v + 6 * r + 5);
                float4 y0 = __ldg(p1v + 6 * r + 0);
                float4 y1 = __ldg(p1v + 6 * r + 1);
                float4 y2 = __ldg(p1v + 6 * r + 2);
                res[0]  = fmaf(a0[r], x0.x, fmaf(a1[r], y0.x, res[0]));
                res[1]  = fmaf(a0[r], x0.y, fmaf(a1[r], y0.y, res[1]));
                res[2]  = fmaf(a0[r], x0.z, fmaf(a1[r], y0.z, res[2]));
                res[3]  = fmaf(a0[r], x0.w, fmaf(a1[r], y0.w, res[3]));
                res[4]  = fmaf(a0[r], x1.x, fmaf(a1[r], y1.x, res[4]));
                res[5]  = fmaf(a0[r], x1.y, fmaf(a1[r], y1.y, res[5]));
                res[6]  = fmaf(a0[r], x1.z, fmaf(a1[r], y1.z, res[6]));
                res[7]  = fmaf(a0[r], x1.w, fmaf(a1[r], y1.w, res[7]));
                res[8]  = fmaf(a0[r], x2.x, fmaf(a1[r], y2.x, res[8]));
                res[9]  = fmaf(a0[r], x2.y, fmaf(a1[r], y2.y, res[9]));
                res[10] = fmaf(a0[r], x2.z, fmaf(a1[r], y2.z, res[10]));
                res[11] = fmaf(a0[r], x2.w, fmaf(a1[r], y2.w, res[11]));
            }
            float4* op = reinterpret_cast<float4*>(
                out + ((size_t)(b * E_ + e0 + el) * AOUT + i) * AOUT);
            op[0] = make_float4(0.5f * res[0], 0.5f * res[1], 0.5f * res[2],  0.5f * res[3]);
            op[1] = make_float4(0.5f * res[4], 0.5f * res[5], 0.5f * res[6],  0.5f * res[7]);
            op[2] = make_float4(0.5f * res[8], 0.5f * res[9], 0.5f * res[10], 0.5f * res[11]);
        }
    }
}

// -------- launch --------
extern "C" void kernel_launch(void* const* d_in, const int* in_sizes, int n_in,
                              void* d_out, int out_size) {
    const float* h  = (const float*)d_in[0];
    const float* W1 = (const float*)d_in[1];
    const float* b1 = (const float*)d_in[2];
    const float* W2 = (const float*)d_in[3];
    const float* b2 = (const float*)d_in[4];
    const int*   ef = (const int*)d_in[5];
    const int*   et = (const int*)d_in[6];
    float* out = (float*)d_out;

    cudaFuncSetAttribute(node_proj, cudaFuncAttributeMaxDynamicSharedMemorySize, SMEM_NP);
    cudaFuncSetAttribute(edge_gemm, cudaFuncAttributeMaxDynamicSharedMemorySize, SMEM_EDGE);

    int dev = 0, nsm = 148;
    cudaGetDevice(&dev);
    cudaDeviceGetAttribute(&nsm, cudaDevAttrMultiProcessorCount, dev);
    if (nsm > MAXSM) nsm = MAXSM;
    if (nsm > TILES_TOTAL) nsm = TILES_TOTAL;

    prep_all<<<97, 256>>>(W2, ef, et);
    node_proj<<<dim3(KH / JTILE, B_), 256, SMEM_NP>>>(h, W1, b1);
    edge_gemm<<<nsm, 512, SMEM_EDGE>>>(b2, out);
}

// round 14
// speedup vs baseline: 1.3305x; 1.0857x over previous
#include <cuda_runtime.h>
#include <cuda_bf16.h>
#include <cstdint>

#define B_    256
#define N_    32
#define DH_   128
#define E_    496
#define KH    256     // DIM_HID
#define NO    96      // DIM_OUT
#define AOUT  12
#define ETILE 62      // edges per tile-job
#define MR    124     // 2*ETILE real rows
#define MPAD  128
#define JTILE 64
#define LDW1I 258
#define TILES_TOTAL 2048
#define LDPS  100     // Ps pitch in floats (400B, 16B-aligned rows)

#define A_REGION (MPAD * 1024)            // 131072
#define B_REGION (NO * 1024)              // 98304
#define SMEM_EDGE (A_REGION + B_REGION)   // 229376
#define SMEM_NP  ((N_ * DH_ + JTILE * LDW1I) * 4)
#define PS_ROWS_B 50                      // B rows overlaid by Ps (50*1024 >= 124*400)

// -------- device scratch --------
__device__ float g_u[2u * B_ * N_ * KH];                    // [s][b][n][k]; s0 has +b1 folded
__device__ __align__(16) unsigned char g_w2i[NO * 1024];    // W2 hi/lo bf16 interleaved, swizzled
__device__ int g_ef[E_], g_et[E_];

// -------- helpers --------
__device__ __forceinline__ uint32_t smem_u32(const void* p) {
    uint32_t a;
    asm("{ .reg .u64 t; cvta.to.shared.u64 t, %1; cvt.u32.u64 %0, t; }" : "=r"(a) : "l"(p));
    return a;
}
__device__ __forceinline__ void cp_async16(uint32_t dst, const void* src) {
    asm volatile("cp.async.cg.shared.global [%0], [%1], 16;" :: "r"(dst), "l"(src) : "memory");
}
__device__ __forceinline__ void mma16816(float* c,
                                         uint32_t a0, uint32_t a1, uint32_t a2, uint32_t a3,
                                         uint32_t b0, uint32_t b1) {
    asm volatile(
        "mma.sync.aligned.m16n8k16.row.col.f32.bf16.bf16.f32 "
        "{%0,%1,%2,%3}, {%4,%5,%6,%7}, {%8,%9}, {%0,%1,%2,%3};"
        : "+f"(c[0]), "+f"(c[1]), "+f"(c[2]), "+f"(c[3])
        : "r"(a0), "r"(a1), "r"(a2), "r"(a3), "r"(b0), "r"(b1));
}
__device__ __forceinline__ uint32_t cvt2bf(float lo, float hi) {
    uint32_t r;
    asm("cvt.rn.bf16x2.f32 %0, %1, %2;" : "=r"(r) : "f"(hi), "f"(lo));
    return r;
}
// f32x2 helpers (node_proj)
__device__ __forceinline__ unsigned long long pk2(float x) {
    unsigned long long r;
    asm("mov.b64 %0, {%1,%2};" : "=l"(r) : "f"(x), "f"(x));
    return r;
}
__device__ __forceinline__ void ffma2(unsigned long long& d,
                                      unsigned long long a, unsigned long long b) {
    asm("fma.rn.f32x2 %0, %1, %2, %0;" : "+l"(d) : "l"(a), "l"(b));
}
__device__ __forceinline__ float2 upk(unsigned long long v) {
    float2 r;
    asm("mov.b64 {%0,%1}, %2;" : "=f"(r.x), "=f"(r.y) : "l"(v));
    return r;
}

// -------- merged prep --------
__global__ void prep_all(const float* __restrict__ W2,
                         const int* __restrict__ efw, const int* __restrict__ etw) {
    if (blockIdx.x == 96) {
        int bad = 0;
        for (int t = threadIdx.x; t < E_; t += blockDim.x)
            if (t & 1)
                if (efw[t] != 0 || etw[t] != 0) bad = 1;
        int is32 = __syncthreads_or(bad);
        for (int e = threadIdx.x; e < E_; e += blockDim.x) {
            g_ef[e] = is32 ? efw[e] : efw[2 * e];
            g_et[e] = is32 ? etw[e] : etw[2 * e];
        }
        return;
    }
    int idx = blockIdx.x * 256 + threadIdx.x;    // n*256 + k
    int n = idx >> 8, k = idx & 255;
    float v = W2[idx];
    __nv_bfloat16 hi = __float2bfloat16(v);
    __nv_bfloat16 lo = __float2bfloat16(v - __bfloat162float(hi));
    uint32_t kp   = (uint32_t)(k >> 1);
    uint32_t phys = kp ^ (((uint32_t)n & 3u) << 2);
    uint32_t cell = (uint32_t)n * 1024 + phys * 8 + (uint32_t)(k & 1) * 2;
    *(__nv_bfloat16*)(g_w2i + cell)     = hi;
    *(__nv_bfloat16*)(g_w2i + cell + 4) = lo;
}

// -------- stage A: node projections, f32x2 packed --------
__global__ void __launch_bounds__(256) node_proj(const float* __restrict__ h,
                                                 const float* __restrict__ W1,
                                                 const float* __restrict__ b1) {
    extern __shared__ float smf[];
    float* hsT = smf;                   // [k][n]: 128 x 32
    float* w1s = smf + N_ * DH_;        // 64 x 258 interleaved {wa,wb}

    int b  = blockIdx.y;
    int j0 = blockIdx.x * JTILE;
    int tid = threadIdx.x;

    for (int i = tid; i < N_ * DH_; i += 256) {
        int n = i >> 7, k = i & 127;
        hsT[k * N_ + n] = h[(size_t)b * N_ * DH_ + i];
    }
    for (int i = tid; i < JTILE * 256; i += 256) {
        int r = i >> 8, c = i & 255;
        w1s[r * LDW1I + ((c & 127) << 1) + (c >> 7)] = W1[(size_t)(j0 + r) * 256 + c];
    }
    __syncthreads();

    int jl = tid & 63;
    int ng = tid >> 6;
    unsigned long long acc[8];
#pragma unroll
    for (int i = 0; i < 8; i++) acc[i] = 0ull;

    const unsigned long long* wrow =
        reinterpret_cast<const unsigned long long*>(w1s + jl * LDW1I);
    const float* hb = hsT + ng * 8;

#pragma unroll 4
    for (int k = 0; k < DH_; k++) {
        unsigned long long w = wrow[k];
        float4 h0 = *(const float4*)(hb + k * N_);
        float4 h1 = *(const float4*)(hb + k * N_ + 4);
        ffma2(acc[0], pk2(h0.x), w);
        ffma2(acc[1], pk2(h0.y), w);
        ffma2(acc[2], pk2(h0.z), w);
        ffma2(acc[3], pk2(h0.w), w);
        ffma2(acc[4], pk2(h1.x), w);
        ffma2(acc[5], pk2(h1.y), w);
        ffma2(acc[6], pk2(h1.z), w);
        ffma2(acc[7], pk2(h1.w), w);
    }

    int j = j0 + jl;
    float b1v = b1[j];
#pragma unroll
    for (int nn = 0; nn < 8; nn++) {
        int n = ng * 8 + nn;
        float2 v = upk(acc[nn]);
        g_u[(size_t)(b * N_ + n) * KH + j] = v.x + b1v;
        g_u[(size_t)B_ * N_ * KH + (size_t)(b * N_ + n) * KH + j] = v.y;
    }
}

// -------- A build for one tile (all 512 threads) --------
__device__ __forceinline__ void build_A(unsigned char* Asm, int b, int e0, int tid) {
    const float* u1b = g_u + (size_t)b * N_ * KH;
    const float* u2b = g_u + (size_t)B_ * N_ * KH + (size_t)b * N_ * KH;
#pragma unroll 4
    for (int i = tid; i < MR * 64; i += 512) {
        int m = i >> 6, kq = i & 63;
        int el = (m < ETILE) ? m : m - ETILE;
        int nf = __ldg(&g_ef[e0 + el]);
        int nt = __ldg(&g_et[e0 + el]);
        if (m >= ETILE) { int tmp = nf; nf = nt; nt = tmp; }
        float4 ua = __ldg((const float4*)(u1b + nf * KH + kq * 4));
        float4 ub = __ldg((const float4*)(u2b + nt * KH + kq * 4));
        float v0 = fmaxf(ua.x + ub.x, 0.f), v1 = fmaxf(ua.y + ub.y, 0.f);
        float v2 = fmaxf(ua.z + ub.z, 0.f), v3 = fmaxf(ua.w + ub.w, 0.f);
        uint4 cell;
        cell.x = cvt2bf(v0, v1);
        cell.z = cvt2bf(v2, v3);
        float h0f = __uint_as_float(cell.x << 16);
        float h1f = __uint_as_float(cell.x & 0xffff0000u);
        float h2f = __uint_as_float(cell.z << 16);
        float h3f = __uint_as_float(cell.z & 0xffff0000u);
        cell.y = cvt2bf(v0 - h0f, v1 - h1f);
        cell.w = cvt2bf(v2 - h2f, v3 - h3f);
        uint32_t phys = ((uint32_t)(kq << 1)) ^ (((uint32_t)m & 3u) << 2);
        *(uint4*)(Asm + (uint32_t)m * 1024 + phys * 8) = cell;
    }
}

// -------- stage B: persistent HMMA bf16x3 GEMM, smem Ps overlaying B-low --------
__global__ void __launch_bounds__(512, 1) edge_gemm(const float* __restrict__ b2,
                                                    float* __restrict__ out) {
    extern __shared__ unsigned char sm[];
    unsigned char* Asm = sm;                    // MPAD x 1024B
    unsigned char* Bsm = sm + A_REGION;         // NO x 1024B
    float* Ps = (float*)Bsm;                    // P overlays B rows 0..49 post-GEMM

    __shared__ float s_b2[NO];

    int tid = threadIdx.x;
    int wid = tid >> 5, lid = tid & 31;
    int bid = blockIdx.x;
    int grid = gridDim.x;
    int nt = (TILES_TOTAL - bid + grid - 1) / grid;

    // ---- init: full B copy once, b2, zero A pad rows ----
    {
        uint32_t bdst = smem_u32(Bsm);
        for (int i = tid; i < B_REGION / 16; i += 512)
            cp_async16(bdst + (uint32_t)i * 16, g_w2i + (uint32_t)i * 16);
        asm volatile("cp.async.commit_group;" ::: "memory");
        if (tid < NO) s_b2[tid] = b2[tid];
        if (tid < 256)
            *(uint4*)(Asm + 124u * 1024 + (uint32_t)tid * 16) = make_uint4(0u, 0u, 0u, 0u);
        asm volatile("cp.async.wait_group 0;" ::: "memory");
    }

    // GEMM lane geometry
    int m0 = (wid >> 2) * 32;
    int n0 = (wid & 3) * 24;
    int lr = lid >> 2;
    int lc = lid & 3;
    uint32_t x4 = ((uint32_t)lr & 3u) << 2;
    uint32_t q  = (uint32_t)lc | (x4 & 4u);
    uint32_t x8 = x4 & 8u;

    const unsigned char* arow0 = Asm + (uint32_t)(m0 + lr) * 1024;
    const unsigned char* arow1 = arow0 + 8 * 1024;
    const unsigned char* arow2 = arow0 + 16 * 1024;
    const unsigned char* arow3 = arow0 + 24 * 1024;
    const unsigned char* brow0 = Bsm + (uint32_t)(n0 + lr) * 1024;
    const unsigned char* brow1 = brow0 + 8 * 1024;
    const unsigned char* brow2 = brow0 + 16 * 1024;

    // prologue: build first tile's A
    {
        int tile = bid;
        build_A(Asm, tile >> 3, (tile & 7) * ETILE, tid);
    }
    __syncthreads();    // A(0) built, B loaded

    for (int it = 0; it < nt; it++) {
        int tile = bid + it * grid;
        int b = tile >> 3, e0 = (tile & 7) * ETILE;

        // ---- GEMM ----
        float acc[2][3][4];
#pragma unroll
        for (int fr = 0; fr < 2; fr++)
#pragma unroll
            for (int t = 0; t < 3; t++)
#pragma unroll
                for (int c = 0; c < 4; c++) acc[fr][t][c] = 0.f;

        uint2 Af[2][8];
        uint2 Bf[2][6];
#define LOAD_FRAGS(buf, st_) do {                                              \
        uint32_t off0 = ((((uint32_t)(st_) << 3) ^ x8) | q) << 3;              \
        uint32_t off4 = off0 ^ 32u;                                            \
        Af[buf][0] = *(const uint2*)(arow0 + off0);                            \
        Af[buf][1] = *(const uint2*)(arow1 + off0);                            \
        Af[buf][2] = *(const uint2*)(arow0 + off4);                            \
        Af[buf][3] = *(const uint2*)(arow1 + off4);                            \
        Af[buf][4] = *(const uint2*)(arow2 + off0);                            \
        Af[buf][5] = *(const uint2*)(arow3 + off0);                            \
        Af[buf][6] = *(const uint2*)(arow2 + off4);                            \
        Af[buf][7] = *(const uint2*)(arow3 + off4);                            \
        Bf[buf][0] = *(const uint2*)(brow0 + off0);                            \
        Bf[buf][1] = *(const uint2*)(brow0 + off4);                            \
        Bf[buf][2] = *(const uint2*)(brow1 + off0);                            \
        Bf[buf][3] = *(const uint2*)(brow1 + off4);                            \
        Bf[buf][4] = *(const uint2*)(brow2 + off0);                            \
        Bf[buf][5] = *(const uint2*)(brow2 + off4);                            \
    } while (0)

        LOAD_FRAGS(0, 0);
#pragma unroll
        for (int st = 0; st < 16; st++) {
            int cur = st & 1;
            if (st < 15) LOAD_FRAGS(cur ^ 1, st + 1);
#pragma unroll
            for (int fr = 0; fr < 2; fr++) {
                uint2 a0 = Af[cur][fr * 4 + 0];
                uint2 a1 = Af[cur][fr * 4 + 1];
                uint2 a2 = Af[cur][fr * 4 + 2];
                uint2 a3 = Af[cur][fr * 4 + 3];
#pragma unroll
                for (int t = 0; t < 3; t++) {
                    uint2 b0 = Bf[cur][t * 2 + 0];
                    uint2 b1 = Bf[cur][t * 2 + 1];
                    mma16816(acc[fr][t], a0.x, a1.x, a2.x, a3.x, b0.x, b1.x);
                    mma16816(acc[fr][t], a0.y, a1.y, a2.y, a3.y, b0.x, b1.x);
                    mma16816(acc[fr][t], a0.x, a1.x, a2.x, a3.x, b0.y, b1.y);
                }
            }
        }
#undef LOAD_FRAGS

        __syncthreads();    // all B/A reads done

        // ---- epilogue: acc (+b2) -> Ps (smem, overlays B rows 0..49) ----
#pragma unroll
        for (int fr = 0; fr < 2; fr++) {
#pragma unroll
            for (int t = 0; t < 3; t++) {
                int mrow = m0 + fr * 16 + lr;
                int col  = n0 + t * 8 + lc * 2;
                float bx = s_b2[col], by = s_b2[col + 1];
                if (mrow < MR)
                    *(float2*)(Ps + mrow * LDPS + col) =
                        make_float2(acc[fr][t][0] + bx, acc[fr][t][1] + by);
                if (mrow + 8 < MR)
                    *(float2*)(Ps + (mrow + 8) * LDPS + col) =
                        make_float2(acc[fr][t][2] + bx, acc[fr][t][3] + by);
            }
        }
        __syncthreads();    // Ps visible

        // ---- build next tile's A (overlaps payoff below) ----
        if (it + 1 < nt) {
            int tile2 = bid + (it + 1) * grid;
            build_A(Asm, tile2 >> 3, (tile2 & 7) * ETILE, tid);
        }

        // ---- payoff from smem Ps ----
        for (int pr = tid; pr < ETILE * AOUT; pr += 512) {
            int el = pr / AOUT;
            int i  = pr - el * AOUT;
            const float*  P0  = Ps + el * LDPS;
            const float*  P1  = P0 + ETILE * LDPS;
            const float4* p0v = (const float4*)P0;
            const float4* p1v = (const float4*)P1;
            float a0[4], a1[4];
#pragma unroll
            for (int r = 0; r < 4; r++) {
                a0[r] = P0[24 * r + i];
                a1[r] = P1[24 * r + 12 + i];
            }
            float res[12];
#pragma unroll
            for (int j = 0; j < 12; j++) res[j] = 0.f;
#pragma unroll
            for (int r = 0; r < 4; r++) {
                float4 x0 = p0v[6 * r + 3];
                float4 x1 = p0v[6 * r + 4];
                float4 x2 = p0v[6 * r + 5];
                float4 y0 = p1v[6 * r + 0];
                float4 y1 = p1v[6 * r + 1];
                float4 y2 = p1v[6 * r + 2];
                res[0]  = fmaf(a0[r], x0.x, fmaf(a1[r], y0.x, res[0]));
                res[1]  = fmaf(a0[r], x0.y, fmaf(a1[r], y0.y, res[1]));
                res[2]  = fmaf(a0[r], x0.z, fmaf(a1[r], y0.z, res[2]));
                res[3]  = fmaf(a0[r], x0.w, fmaf(a1[r], y0.w, res[3]));
                res[4]  = fmaf(a0[r], x1.x, fmaf(a1[r], y1.x, res[4]));
                res[5]  = fmaf(a0[r], x1.y, fmaf(a1[r], y1.y, res[5]));
                res[6]  = fmaf(a0[r], x1.z, fmaf(a1[r], y1.z, res[6]));
                res[7]  = fmaf(a0[r], x1.w, fmaf(a1[r], y1.w, res[7]));
                res[8]  = fmaf(a0[r], x2.x, fmaf(a1[r], y2.x, res[8]));
                res[9]  = fmaf(a0[r], x2.y, fmaf(a1[r], y2.y, res[9]));
                res[10] = fmaf(a0[r], x2.z, fmaf(a1[r], y2.z, res[10]));
                res[11] = fmaf(a0[r], x2.w, fmaf(a1[r], y2.w, res[11]));
            }
            float4* op = reinterpret_cast<float4*>(
                out + ((size_t)(b * E_ + e0 + el) * AOUT + i) * AOUT);
            op[0] = make_float4(0.5f * res[0], 0.5f * res[1], 0.5f * res[2],  0.5f * res[3]);
            op[1] = make_float4(0.5f * res[4], 0.5f * res[5], 0.5f * res[6],  0.5f * res[7]);
            op[2] = make_float4(0.5f * res[8], 0.5f * res[9], 0.5f * res[10], 0.5f * res[11]);
        }
        __syncthreads();    // Ps reads done; A(t+1) build visible

        // ---- refill B rows 0..49 (overwritten by Ps) ----
        if (it + 1 < nt) {
            uint32_t bdst = smem_u32(Bsm);
            for (int i = tid; i < (PS_ROWS_B * 1024) / 16; i += 512)
                cp_async16(bdst + (uint32_t)i * 16, g_w2i + (uint32_t)i * 16);
            asm volatile("cp.async.commit_group;" ::: "memory");
            asm volatile("cp.async.wait_group 0;" ::: "memory");
            __syncthreads();    // B restored + visible
        }
    }
}

// -------- launch --------
extern "C" void kernel_launch(void* const* d_in, const int* in_sizes, int n_in,
                              void* d_out, int out_size) {
    const float* h  = (const float*)d_in[0];
    const float* W1 = (const float*)d_in[1];
    const float* b1 = (const float*)d_in[2];
    const float* W2 = (const float*)d_in[3];
    const float* b2 = (const float*)d_in[4];
    const int*   ef = (const int*)d_in[5];
    const int*   et = (const int*)d_in[6];
    float* out = (float*)d_out;

    cudaFuncSetAttribute(node_proj, cudaFuncAttributeMaxDynamicSharedMemorySize, SMEM_NP);
    cudaFuncSetAttribute(edge_gemm, cudaFuncAttributeMaxDynamicSharedMemorySize, SMEM_EDGE);

    int dev = 0, nsm = 148;
    cudaGetDevice(&dev);
    cudaDeviceGetAttribute(&nsm, cudaDevAttrMultiProcessorCount, dev);
    if (nsm > TILES_TOTAL) nsm = TILES_TOTAL;

    prep_all<<<97, 256>>>(W2, ef, et);
    node_proj<<<dim3(KH / JTILE, B_), 256, SMEM_NP>>>(h, W1, b1);
    edge_gemm<<<nsm, 512, SMEM_EDGE>>>(b2, out);
}